// round 10
// baseline (speedup 1.0000x reference)
#include <cuda_runtime.h>
#include <cstdint>
#include <math.h>

#define BDIM 2
#define TLEN 2048
#define CDIM 1024
#define NH   16
#define DH   64
#define MROWS (BDIM * TLEN)   // 4096

// Scratch (allocation-free rule: __device__ globals)
__device__ float g_q[(size_t)BDIM * NH * TLEN * DH];   // tf32-rounded, pre-scaled
__device__ float g_k[(size_t)BDIM * NH * TLEN * DH];   // tf32-rounded
__device__ float g_v[(size_t)BDIM * NH * TLEN * DH];   // tf32-rounded
__device__ float g_att[(size_t)MROWS * CDIM];          // [B,T,C], tf32-rounded
__device__ float g_xr[(size_t)MROWS * CDIM];           // tf32-rounded x
__device__ float g_wr[4][(size_t)CDIM * CDIM];         // tf32-rounded Wq,Wk,Wv,Wo

// ============================================================================
// helpers
// ============================================================================
__device__ __forceinline__ float f2tf32f(float f) {
    uint32_t r;
    asm("cvt.rna.tf32.f32 %0, %1;" : "=r"(r) : "f"(f));
    return __uint_as_float(r);
}
__device__ __forceinline__ float4 cvt4(float4 v) {
    return make_float4(f2tf32f(v.x), f2tf32f(v.y), f2tf32f(v.z), f2tf32f(v.w));
}
__device__ __forceinline__ void mma_tf32(float* d, const uint32_t* a,
                                         const uint32_t* b) {
    asm volatile(
        "mma.sync.aligned.m16n8k8.row.col.f32.tf32.tf32.f32 "
        "{%0,%1,%2,%3}, {%4,%5,%6,%7}, {%8,%9}, {%0,%1,%2,%3};"
        : "+f"(d[0]), "+f"(d[1]), "+f"(d[2]), "+f"(d[3])
        : "r"(a[0]), "r"(a[1]), "r"(a[2]), "r"(a[3]), "r"(b[0]), "r"(b[1]));
}
__device__ __forceinline__ uint32_t smem_u32(const void* p) {
    uint32_t a;
    asm("{ .reg .u64 t; cvta.to.shared.u64 t, %1; cvt.u32.u64 %0, t; }"
        : "=r"(a) : "l"(p));
    return a;
}
__device__ __forceinline__ void cp_async16(uint32_t saddr, const void* gptr) {
    asm volatile("cp.async.ca.shared.global [%0], [%1], 16;"
                 :: "r"(saddr), "l"(gptr) : "memory");
}
__device__ __forceinline__ void cp_commit() {
    asm volatile("cp.async.commit_group;" ::: "memory");
}

// ============================================================================
// preround: tf32-round x and the 4 weight matrices into scratch
// ============================================================================
__global__ void __launch_bounds__(256) preround_kernel(
    const float* __restrict__ x,  const float* __restrict__ Wq,
    const float* __restrict__ Wk, const float* __restrict__ Wv,
    const float* __restrict__ Wo)
{
    const int t = blockIdx.y;
    const float* src;
    float* dst;
    int n;
    if (t == 0) { src = x; dst = g_xr; n = MROWS * CDIM / 4; }
    else {
        src = (t == 1) ? Wq : (t == 2) ? Wk : (t == 3) ? Wv : Wo;
        dst = g_wr[t - 1];
        n = CDIM * CDIM / 4;
    }
    int idx = blockIdx.x * 256 + threadIdx.x;
    if (idx < n) ((float4*)dst)[idx] = cvt4(((const float4*)src)[idx]);
}

// ============================================================================
// cp.async 3-stage tf32 mma.sync GEMM.
// SCATTER=1: epilogue tf32-rounds outputs; q additionally pre-scaled 0.125.
// SCATTER=0: plain fp32 write (final output).
// ============================================================================
#define BK2 32
#define LDT2 36
#define STAGES 3
#define NSTEP2 (CDIM / BK2)     // 32
#define GSMEM2 (STAGES * 128 * LDT2 * 2 * 4)   // 110592 B

template <int SCATTER>
__global__ void __launch_bounds__(256, 2) gemm_cp_kernel(float* __restrict__ Cout)
{
    extern __shared__ float smf[];
    const int K = CDIM;
    float* As = smf;                           // [STAGES][128][LDT2]
    float* Ws = smf + STAGES * 128 * LDT2;

    const float* Ap = SCATTER ? g_xr : g_att;
    const float* W  = g_wr[SCATTER ? blockIdx.z : 3];
    float* dst;
    if (SCATTER) {
        int z = blockIdx.z;
        dst = (z == 0) ? g_q : (z == 1) ? g_k : g_v;
    } else {
        dst = Cout;
    }
    const float oscale = (SCATTER && blockIdx.z == 0) ? 0.125f : 1.0f;

    const int bm0  = blockIdx.y * 128;
    const int bn0  = blockIdx.x * 128;
    const int tid  = threadIdx.x;
    const int lane = tid & 31;
    const int wid  = tid >> 5;
    const int g    = lane >> 2;
    const int tig  = lane & 3;
    const int wm   = (wid & 3) * 32;
    const int wn   = (wid >> 2) * 64;

    const uint32_t sbA = smem_u32(As);
    const uint32_t sbW = smem_u32(Ws);

    float d[2][8][4];
#pragma unroll
    for (int mc = 0; mc < 2; mc++)
#pragma unroll
        for (int nc = 0; nc < 8; nc++)
#pragma unroll
            for (int v = 0; v < 4; v++) d[mc][nc][v] = 0.f;

    auto issue = [&](int t, int slot) {
        const int k0 = t * BK2;
        const uint32_t ab = sbA + slot * 128 * LDT2 * 4;
        const uint32_t wb = sbW + slot * 128 * LDT2 * 4;
#pragma unroll
        for (int l = 0; l < 4; l++) {
            int idx = tid + l * 256;      // 0..1023
            int r   = idx >> 3;           // 0..127
            int c   = idx & 7;
            uint32_t so = (uint32_t)(r * LDT2 + c * 4) * 4;
            cp_async16(ab + so, &Ap[(size_t)(bm0 + r) * K + k0 + c * 4]);
            cp_async16(wb + so, &W [(size_t)(bn0 + r) * K + k0 + c * 4]);
        }
        cp_commit();
    };

    issue(0, 0);
    issue(1, 1);

    for (int s = 0; s < NSTEP2; s++) {
        if (s + 1 < NSTEP2) asm volatile("cp.async.wait_group 1;" ::: "memory");
        else                asm volatile("cp.async.wait_group 0;" ::: "memory");
        __syncthreads();
        if (s + 2 < NSTEP2) issue(s + 2, (s + 2) % STAGES);

        const float* Ab = As + (s % STAGES) * 128 * LDT2;
        const float* Wb = Ws + (s % STAGES) * 128 * LDT2;
#pragma unroll
        for (int kk8 = 0; kk8 < 4; kk8++) {
            const int kk = kk8 * 8;
            uint32_t a[2][4];
#pragma unroll
            for (int mc = 0; mc < 2; mc++) {
                int row = wm + mc * 16 + g;
                a[mc][0] = __float_as_uint(Ab[(row    ) * LDT2 + kk + tig]);
                a[mc][1] = __float_as_uint(Ab[(row + 8) * LDT2 + kk + tig]);
                a[mc][2] = __float_as_uint(Ab[(row    ) * LDT2 + kk + tig + 4]);
                a[mc][3] = __float_as_uint(Ab[(row + 8) * LDT2 + kk + tig + 4]);
            }
#pragma unroll
            for (int nc = 0; nc < 8; nc++) {
                uint32_t b[2];
                int row = wn + nc * 8 + g;
                b[0] = __float_as_uint(Wb[row * LDT2 + kk + tig]);
                b[1] = __float_as_uint(Wb[row * LDT2 + kk + tig + 4]);
                mma_tf32(d[0][nc], a[0], b);
                mma_tf32(d[1][nc], a[1], b);
            }
        }
    }

#pragma unroll
    for (int mc = 0; mc < 2; mc++) {
#pragma unroll
        for (int nc = 0; nc < 8; nc++) {
            int n = bn0 + wn + nc * 8 + tig * 2;
#pragma unroll
            for (int rr = 0; rr < 2; rr++) {
                int m = bm0 + wm + mc * 16 + g + rr * 8;
                float2 val;
                if (SCATTER) {
                    val = make_float2(f2tf32f(d[mc][nc][rr * 2 + 0] * oscale),
                                      f2tf32f(d[mc][nc][rr * 2 + 1] * oscale));
                    int bb = m >> 11;
                    int tt = m & 2047;
                    int hh = n >> 6;
                    int dd = n & 63;
                    *(float2*)&dst[(((size_t)bb * NH + hh) * TLEN + tt) * DH + dd] = val;
                } else {
                    val = make_float2(d[mc][nc][rr * 2 + 0], d[mc][nc][rr * 2 + 1]);
                    *(float2*)&dst[(size_t)m * CDIM + n] = val;
                }
            }
        }
    }
}

// ============================================================================
// tf32 mma.sync causal flash attention v4 — register-resident P + cp.async.
// q/k/v are pre-rounded (q pre-scaled) by gemm<1>, so tiles stream into smem
// via cp.async with zero in-thread staging work. 3 CTAs/SM.
// ============================================================================
#define LDQ 68
#define LDK 68
#define LDV 68
#define QROWS 128
// floats: qs 128*68 + ks 64*68 + vs 64*68 = 17408
#define ATT_SMEM (17408 * 4)    // 69632 B

__global__ void __launch_bounds__(256, 3) attn_mma_kernel()
{
    extern __shared__ float sm[];
    float* qs = sm;                         // [128][LDQ]
    float* ks = qs + QROWS * LDQ;           // [64][LDK]
    float* vs = ks + 64 * LDK;              // [64][LDV]
    const uint32_t sq = smem_u32(qs);
    const uint32_t sk = smem_u32(ks);
    const uint32_t sv = smem_u32(vs);

    const int qt = (gridDim.x - 1) - blockIdx.x;   // big tiles first
    const int bh = blockIdx.y;
    const float* qg = g_q + (size_t)bh * TLEN * DH;
    const float* kg = g_k + (size_t)bh * TLEN * DH;
    const float* vg = g_v + (size_t)bh * TLEN * DH;

    const int tid  = threadIdx.x;
    const int lane = tid & 31;
    const int wid  = tid >> 5;
    const int g    = lane >> 2;
    const int tig  = lane & 3;

    // stage Q tile via cp.async (pre-rounded, pre-scaled): 2048 chunks
#pragma unroll
    for (int l = 0; l < 8; l++) {
        int idx = tid + l * 256;
        int r   = idx >> 4;
        int c   = idx & 15;
        cp_async16(sq + (uint32_t)(r * LDQ + c * 4) * 4,
                   &qg[(size_t)(qt * QROWS + r) * DH + c * 4]);
    }
    cp_commit();

    const int wrow = qt * QROWS + wid * 16;
    float mrow0 = -INFINITY, mrow1 = -INFINITY;
    float lrow0 = 0.f, lrow1 = 0.f;
    float o[8][4];
#pragma unroll
    for (int nc = 0; nc < 8; nc++)
#pragma unroll
        for (int v = 0; v < 4; v++) o[nc][v] = 0.f;

    const int ktmax = 2 * qt + 1;
    for (int kt = 0; kt <= ktmax; kt++) {
        // K/V tile via cp.async: 1024 chunks each, 4+4 per thread
#pragma unroll
        for (int l = 0; l < 4; l++) {
            int idx = tid + l * 256;
            int r   = idx >> 4;
            int c   = idx & 15;
            cp_async16(sk + (uint32_t)(r * LDK + c * 4) * 4,
                       &kg[(size_t)(kt * 64 + r) * DH + c * 4]);
            cp_async16(sv + (uint32_t)(r * LDV + c * 4) * 4,
                       &vg[(size_t)(kt * 64 + r) * DH + c * 4]);
        }
        cp_commit();
        asm volatile("cp.async.wait_group 0;" ::: "memory");
        __syncthreads();

        if (kt * 64 <= wrow + 15) {
            // ---- S = Q K^T ----
            float s[8][4];
#pragma unroll
            for (int nc = 0; nc < 8; nc++)
#pragma unroll
                for (int v = 0; v < 4; v++) s[nc][v] = 0.f;
#pragma unroll
            for (int kk8 = 0; kk8 < 8; kk8++) {
                const int kk = kk8 * 8;
                uint32_t a[4];
                a[0] = __float_as_uint(qs[(wid * 16 + g    ) * LDQ + kk + tig]);
                a[1] = __float_as_uint(qs[(wid * 16 + g + 8) * LDQ + kk + tig]);
                a[2] = __float_as_uint(qs[(wid * 16 + g    ) * LDQ + kk + tig + 4]);
                a[3] = __float_as_uint(qs[(wid * 16 + g + 8) * LDQ + kk + tig + 4]);
#pragma unroll
                for (int nc = 0; nc < 8; nc++) {
                    uint32_t b[2];
                    b[0] = __float_as_uint(ks[(nc * 8 + g) * LDK + kk + tig]);
                    b[1] = __float_as_uint(ks[(nc * 8 + g) * LDK + kk + tig + 4]);
                    mma_tf32(s[nc], a, b);
                }
            }

            // ---- causal mask ----
            if (kt * 64 + 63 > wrow) {
#pragma unroll
                for (int nc = 0; nc < 8; nc++) {
                    int col = kt * 64 + nc * 8 + 2 * tig;
                    if (col     > wrow + g)     s[nc][0] = -INFINITY;
                    if (col + 1 > wrow + g)     s[nc][1] = -INFINITY;
                    if (col     > wrow + g + 8) s[nc][2] = -INFINITY;
                    if (col + 1 > wrow + g + 8) s[nc][3] = -INFINITY;
                }
            }

            // ---- warp-local online softmax (P stays in s registers) ----
            float t0 = -INFINITY, t1 = -INFINITY;
#pragma unroll
            for (int nc = 0; nc < 8; nc++) {
                t0 = fmaxf(t0, fmaxf(s[nc][0], s[nc][1]));
                t1 = fmaxf(t1, fmaxf(s[nc][2], s[nc][3]));
            }
            t0 = fmaxf(t0, __shfl_xor_sync(0xffffffffu, t0, 1));
            t0 = fmaxf(t0, __shfl_xor_sync(0xffffffffu, t0, 2));
            t1 = fmaxf(t1, __shfl_xor_sync(0xffffffffu, t1, 1));
            t1 = fmaxf(t1, __shfl_xor_sync(0xffffffffu, t1, 2));
            float mn0 = fmaxf(mrow0, t0);
            float mn1 = fmaxf(mrow1, t1);
            float sc0 = __expf(mrow0 - mn0);
            float sc1 = __expf(mrow1 - mn1);
            mrow0 = mn0; mrow1 = mn1;

            float rs0 = 0.f, rs1 = 0.f;
#pragma unroll
            for (int nc = 0; nc < 8; nc++) {
                s[nc][0] = f2tf32f(__expf(s[nc][0] - mn0));
                s[nc][1] = f2tf32f(__expf(s[nc][1] - mn0));
                s[nc][2] = f2tf32f(__expf(s[nc][2] - mn1));
                s[nc][3] = f2tf32f(__expf(s[nc][3] - mn1));
                rs0 += s[nc][0] + s[nc][1];
                rs1 += s[nc][2] + s[nc][3];
            }
            rs0 += __shfl_xor_sync(0xffffffffu, rs0, 1);
            rs0 += __shfl_xor_sync(0xffffffffu, rs0, 2);
            rs1 += __shfl_xor_sync(0xffffffffu, rs1, 1);
            rs1 += __shfl_xor_sync(0xffffffffu, rs1, 2);
            lrow0 = lrow0 * sc0 + rs0;
            lrow1 = lrow1 * sc1 + rs1;
#pragma unroll
            for (int nc = 0; nc < 8; nc++) {
                o[nc][0] *= sc0; o[nc][1] *= sc0;
                o[nc][2] *= sc1; o[nc][3] *= sc1;
            }

            // ---- O += P V (A-fragment from s regs, permuted V rows) ----
#pragma unroll
            for (int j = 0; j < 8; j++) {
                uint32_t a[4];
                a[0] = __float_as_uint(s[j][0]);
                a[1] = __float_as_uint(s[j][2]);
                a[2] = __float_as_uint(s[j][1]);
                a[3] = __float_as_uint(s[j][3]);
                const int vr0 = j * 8 + 2 * tig;     // sigma(8j + tig)
#pragma unroll
                for (int nc = 0; nc < 8; nc++) {
                    uint32_t b[2];
                    b[0] = __float_as_uint(vs[(vr0    ) * LDV + nc * 8 + g]);
                    b[1] = __float_as_uint(vs[(vr0 + 1) * LDV + nc * 8 + g]);
                    mma_tf32(o[nc], a, b);
                }
            }
        }
        __syncthreads();
    }

    // normalize, tf32-round, write g_att [B,T,C]
    const int b = bh >> 4;
    const int h = bh & 15;
    const float inv0 = 1.f / lrow0;
    const float inv1 = 1.f / lrow1;
    const int t0r = wrow + g;
    const int t1r = wrow + g + 8;
#pragma unroll
    for (int nc = 0; nc < 8; nc++) {
        int d = h * DH + nc * 8 + 2 * tig;
        *(float2*)&g_att[((size_t)b * TLEN + t0r) * CDIM + d] =
            make_float2(f2tf32f(o[nc][0] * inv0), f2tf32f(o[nc][1] * inv0));
        *(float2*)&g_att[((size_t)b * TLEN + t1r) * CDIM + d] =
            make_float2(f2tf32f(o[nc][2] * inv1), f2tf32f(o[nc][3] * inv1));
    }
}

// ----------------------------------------------------------------------------
extern "C" void kernel_launch(void* const* d_in, const int* in_sizes, int n_in,
                              void* d_out, int out_size)
{
    const float* x  = (const float*)d_in[0];
    const float* Wq = (const float*)d_in[1];
    const float* Wk = (const float*)d_in[2];
    const float* Wv = (const float*)d_in[3];
    const float* Wo = (const float*)d_in[4];
    float* out = (float*)d_out;

    preround_kernel<<<dim3(4096, 5), 256>>>(x, Wq, Wk, Wv, Wo);

    cudaFuncSetAttribute(gemm_cp_kernel<1>,
                         cudaFuncAttributeMaxDynamicSharedMemorySize, GSMEM2);
    cudaFuncSetAttribute(gemm_cp_kernel<0>,
                         cudaFuncAttributeMaxDynamicSharedMemorySize, GSMEM2);

    gemm_cp_kernel<1><<<dim3(CDIM / 128, MROWS / 128, 3), 256, GSMEM2>>>(nullptr);

    cudaFuncSetAttribute(attn_mma_kernel,
                         cudaFuncAttributeMaxDynamicSharedMemorySize, ATT_SMEM);
    attn_mma_kernel<<<dim3(TLEN / QROWS, BDIM * NH), 256, ATT_SMEM>>>();

    gemm_cp_kernel<0><<<dim3(CDIM / 128, MROWS / 128, 1), 256, GSMEM2>>>(out);
}

// round 11
// speedup vs baseline: 1.0534x; 1.0534x over previous
#include <cuda_runtime.h>
#include <cstdint>
#include <math.h>

#define BDIM 2
#define TLEN 2048
#define CDIM 1024
#define NH   16
#define DH   64
#define MROWS (BDIM * TLEN)   // 4096

// Scratch (allocation-free rule: __device__ globals)
__device__ float g_q[(size_t)BDIM * NH * TLEN * DH];   // tf32-rounded, pre-scaled
__device__ float g_k[(size_t)BDIM * NH * TLEN * DH];   // tf32-rounded
__device__ float g_v[(size_t)BDIM * NH * TLEN * DH];   // tf32-rounded
__device__ float g_att[(size_t)MROWS * CDIM];          // [B,T,C], tf32-rounded
__device__ float g_xr[(size_t)MROWS * CDIM];           // tf32-rounded x
__device__ float g_wr[4][(size_t)CDIM * CDIM];         // tf32-rounded Wq,Wk,Wv,Wo

// ============================================================================
// helpers
// ============================================================================
__device__ __forceinline__ float f2tf32f(float f) {
    uint32_t r;
    asm("cvt.rna.tf32.f32 %0, %1;" : "=r"(r) : "f"(f));
    return __uint_as_float(r);
}
__device__ __forceinline__ float4 cvt4(float4 v) {
    return make_float4(f2tf32f(v.x), f2tf32f(v.y), f2tf32f(v.z), f2tf32f(v.w));
}
__device__ __forceinline__ void mma_tf32(float* d, const uint32_t* a,
                                         const uint32_t* b) {
    asm volatile(
        "mma.sync.aligned.m16n8k8.row.col.f32.tf32.tf32.f32 "
        "{%0,%1,%2,%3}, {%4,%5,%6,%7}, {%8,%9}, {%0,%1,%2,%3};"
        : "+f"(d[0]), "+f"(d[1]), "+f"(d[2]), "+f"(d[3])
        : "r"(a[0]), "r"(a[1]), "r"(a[2]), "r"(a[3]), "r"(b[0]), "r"(b[1]));
}
__device__ __forceinline__ uint32_t smem_u32(const void* p) {
    uint32_t a;
    asm("{ .reg .u64 t; cvta.to.shared.u64 t, %1; cvt.u32.u64 %0, t; }"
        : "=r"(a) : "l"(p));
    return a;
}
__device__ __forceinline__ void cp_async16(uint32_t saddr, const void* gptr) {
    asm volatile("cp.async.ca.shared.global [%0], [%1], 16;"
                 :: "r"(saddr), "l"(gptr) : "memory");
}
__device__ __forceinline__ void cp_commit() {
    asm volatile("cp.async.commit_group;" ::: "memory");
}

// ============================================================================
// preround: tf32-round x and the 4 weight matrices into scratch
// ============================================================================
__global__ void __launch_bounds__(256) preround_kernel(
    const float* __restrict__ x,  const float* __restrict__ Wq,
    const float* __restrict__ Wk, const float* __restrict__ Wv,
    const float* __restrict__ Wo)
{
    const int t = blockIdx.y;
    const float* src;
    float* dst;
    int n;
    if (t == 0) { src = x; dst = g_xr; n = MROWS * CDIM / 4; }
    else {
        src = (t == 1) ? Wq : (t == 2) ? Wk : (t == 3) ? Wv : Wo;
        dst = g_wr[t - 1];
        n = CDIM * CDIM / 4;
    }
    int idx = blockIdx.x * 256 + threadIdx.x;
    if (idx < n) ((float4*)dst)[idx] = cvt4(((const float4*)src)[idx]);
}

// ============================================================================
// cp.async 3-stage tf32 mma.sync GEMM (unchanged from round 10).
// SCATTER=1: epilogue tf32-rounds outputs; q additionally pre-scaled 0.125.
// ============================================================================
#define BK2 32
#define LDT2 36
#define STAGES 3
#define NSTEP2 (CDIM / BK2)     // 32
#define GSMEM2 (STAGES * 128 * LDT2 * 2 * 4)   // 110592 B

template <int SCATTER>
__global__ void __launch_bounds__(256, 2) gemm_cp_kernel(float* __restrict__ Cout)
{
    extern __shared__ float smf[];
    const int K = CDIM;
    float* As = smf;                           // [STAGES][128][LDT2]
    float* Ws = smf + STAGES * 128 * LDT2;

    const float* Ap = SCATTER ? g_xr : g_att;
    const float* W  = g_wr[SCATTER ? blockIdx.z : 3];
    float* dst;
    if (SCATTER) {
        int z = blockIdx.z;
        dst = (z == 0) ? g_q : (z == 1) ? g_k : g_v;
    } else {
        dst = Cout;
    }
    const float oscale = (SCATTER && blockIdx.z == 0) ? 0.125f : 1.0f;

    const int bm0  = blockIdx.y * 128;
    const int bn0  = blockIdx.x * 128;
    const int tid  = threadIdx.x;
    const int lane = tid & 31;
    const int wid  = tid >> 5;
    const int g    = lane >> 2;
    const int tig  = lane & 3;
    const int wm   = (wid & 3) * 32;
    const int wn   = (wid >> 2) * 64;

    const uint32_t sbA = smem_u32(As);
    const uint32_t sbW = smem_u32(Ws);

    float d[2][8][4];
#pragma unroll
    for (int mc = 0; mc < 2; mc++)
#pragma unroll
        for (int nc = 0; nc < 8; nc++)
#pragma unroll
            for (int v = 0; v < 4; v++) d[mc][nc][v] = 0.f;

    auto issue = [&](int t, int slot) {
        const int k0 = t * BK2;
        const uint32_t ab = sbA + slot * 128 * LDT2 * 4;
        const uint32_t wb = sbW + slot * 128 * LDT2 * 4;
#pragma unroll
        for (int l = 0; l < 4; l++) {
            int idx = tid + l * 256;      // 0..1023
            int r   = idx >> 3;           // 0..127
            int c   = idx & 7;
            uint32_t so = (uint32_t)(r * LDT2 + c * 4) * 4;
            cp_async16(ab + so, &Ap[(size_t)(bm0 + r) * K + k0 + c * 4]);
            cp_async16(wb + so, &W [(size_t)(bn0 + r) * K + k0 + c * 4]);
        }
        cp_commit();
    };

    issue(0, 0);
    issue(1, 1);

    for (int s = 0; s < NSTEP2; s++) {
        if (s + 1 < NSTEP2) asm volatile("cp.async.wait_group 1;" ::: "memory");
        else                asm volatile("cp.async.wait_group 0;" ::: "memory");
        __syncthreads();
        if (s + 2 < NSTEP2) issue(s + 2, (s + 2) % STAGES);

        const float* Ab = As + (s % STAGES) * 128 * LDT2;
        const float* Wb = Ws + (s % STAGES) * 128 * LDT2;
#pragma unroll
        for (int kk8 = 0; kk8 < 4; kk8++) {
            const int kk = kk8 * 8;
            uint32_t a[2][4];
#pragma unroll
            for (int mc = 0; mc < 2; mc++) {
                int row = wm + mc * 16 + g;
                a[mc][0] = __float_as_uint(Ab[(row    ) * LDT2 + kk + tig]);
                a[mc][1] = __float_as_uint(Ab[(row + 8) * LDT2 + kk + tig]);
                a[mc][2] = __float_as_uint(Ab[(row    ) * LDT2 + kk + tig + 4]);
                a[mc][3] = __float_as_uint(Ab[(row + 8) * LDT2 + kk + tig + 4]);
            }
#pragma unroll
            for (int nc = 0; nc < 8; nc++) {
                uint32_t b[2];
                int row = wn + nc * 8 + g;
                b[0] = __float_as_uint(Wb[row * LDT2 + kk + tig]);
                b[1] = __float_as_uint(Wb[row * LDT2 + kk + tig + 4]);
                mma_tf32(d[0][nc], a[0], b);
                mma_tf32(d[1][nc], a[1], b);
            }
        }
    }

#pragma unroll
    for (int mc = 0; mc < 2; mc++) {
#pragma unroll
        for (int nc = 0; nc < 8; nc++) {
            int n = bn0 + wn + nc * 8 + tig * 2;
#pragma unroll
            for (int rr = 0; rr < 2; rr++) {
                int m = bm0 + wm + mc * 16 + g + rr * 8;
                float2 val;
                if (SCATTER) {
                    val = make_float2(f2tf32f(d[mc][nc][rr * 2 + 0] * oscale),
                                      f2tf32f(d[mc][nc][rr * 2 + 1] * oscale));
                    int bb = m >> 11;
                    int tt = m & 2047;
                    int hh = n >> 6;
                    int dd = n & 63;
                    *(float2*)&dst[(((size_t)bb * NH + hh) * TLEN + tt) * DH + dd] = val;
                } else {
                    val = make_float2(d[mc][nc][rr * 2 + 0], d[mc][nc][rr * 2 + 1]);
                    *(float2*)&dst[(size_t)m * CDIM + n] = val;
                }
            }
        }
    }
}

// ============================================================================
// tf32 mma.sync causal flash attention v5 — register-resident P +
// double-buffered cp.async K/V pipeline (wait deferred behind compute).
// smem: Q 34816 + 2 x (K+V) 34816 = 104448 B -> 2 CTAs/SM.
// ============================================================================
#define LDQ 68
#define LDK 68
#define LDV 68
#define QROWS 128
#define KVSTAGE (2 * 64 * LDK)          // floats per K+V stage = 8704
#define ATT_SMEM ((QROWS * LDQ + 2 * KVSTAGE) * 4)   // 104448 B

__global__ void __launch_bounds__(256, 2) attn_mma_kernel()
{
    extern __shared__ float sm[];
    float* qs = sm;                          // [128][LDQ]
    float* kvb = qs + QROWS * LDQ;           // [2][ K[64][LDK] | V[64][LDV] ]
    const uint32_t sq  = smem_u32(qs);
    const uint32_t skv = smem_u32(kvb);

    const int qt = (gridDim.x - 1) - blockIdx.x;   // big tiles first
    const int bh = blockIdx.y;
    const float* qg = g_q + (size_t)bh * TLEN * DH;
    const float* kg = g_k + (size_t)bh * TLEN * DH;
    const float* vg = g_v + (size_t)bh * TLEN * DH;

    const int tid  = threadIdx.x;
    const int lane = tid & 31;
    const int wid  = tid >> 5;
    const int g    = lane >> 2;
    const int tig  = lane & 3;

    auto issue_kv = [&](int kt, int b) {
        const uint32_t kb = skv + (uint32_t)(b * KVSTAGE) * 4;
        const uint32_t vb = kb + (uint32_t)(64 * LDK) * 4;
#pragma unroll
        for (int l = 0; l < 4; l++) {
            int idx = tid + l * 256;
            int r   = idx >> 4;
            int c   = idx & 15;
            cp_async16(kb + (uint32_t)(r * LDK + c * 4) * 4,
                       &kg[(size_t)(kt * 64 + r) * DH + c * 4]);
            cp_async16(vb + (uint32_t)(r * LDV + c * 4) * 4,
                       &vg[(size_t)(kt * 64 + r) * DH + c * 4]);
        }
        cp_commit();
    };

    // group 0: Q tile + K/V tile 0
#pragma unroll
    for (int l = 0; l < 8; l++) {
        int idx = tid + l * 256;
        int r   = idx >> 4;
        int c   = idx & 15;
        cp_async16(sq + (uint32_t)(r * LDQ + c * 4) * 4,
                   &qg[(size_t)(qt * QROWS + r) * DH + c * 4]);
    }
    issue_kv(0, 0);

    const int wrow = qt * QROWS + wid * 16;
    float mrow0 = -INFINITY, mrow1 = -INFINITY;
    float lrow0 = 0.f, lrow1 = 0.f;
    float o[8][4];
#pragma unroll
    for (int nc = 0; nc < 8; nc++)
#pragma unroll
        for (int v = 0; v < 4; v++) o[nc][v] = 0.f;

    const int ktmax = 2 * qt + 1;
    for (int kt = 0; kt <= ktmax; kt++) {
        // tile kt is the only outstanding group -> wait it, then barrier
        asm volatile("cp.async.wait_group 0;" ::: "memory");
        __syncthreads();
        // prefetch tile kt+1 into the other buffer (safe: all warps passed
        // the barrier above, so no one still reads that buffer's old data)
        if (kt < ktmax) issue_kv(kt + 1, (kt + 1) & 1);

        const float* ks = kvb + (kt & 1) * KVSTAGE;
        const float* vs = ks + 64 * LDK;

        if (kt * 64 <= wrow + 15) {
            // ---- S = Q K^T ----
            float s[8][4];
#pragma unroll
            for (int nc = 0; nc < 8; nc++)
#pragma unroll
                for (int v = 0; v < 4; v++) s[nc][v] = 0.f;
#pragma unroll
            for (int kk8 = 0; kk8 < 8; kk8++) {
                const int kk = kk8 * 8;
                uint32_t a[4];
                a[0] = __float_as_uint(qs[(wid * 16 + g    ) * LDQ + kk + tig]);
                a[1] = __float_as_uint(qs[(wid * 16 + g + 8) * LDQ + kk + tig]);
                a[2] = __float_as_uint(qs[(wid * 16 + g    ) * LDQ + kk + tig + 4]);
                a[3] = __float_as_uint(qs[(wid * 16 + g + 8) * LDQ + kk + tig + 4]);
#pragma unroll
                for (int nc = 0; nc < 8; nc++) {
                    uint32_t b[2];
                    b[0] = __float_as_uint(ks[(nc * 8 + g) * LDK + kk + tig]);
                    b[1] = __float_as_uint(ks[(nc * 8 + g) * LDK + kk + tig + 4]);
                    mma_tf32(s[nc], a, b);
                }
            }

            // ---- causal mask ----
            if (kt * 64 + 63 > wrow) {
#pragma unroll
                for (int nc = 0; nc < 8; nc++) {
                    int col = kt * 64 + nc * 8 + 2 * tig;
                    if (col     > wrow + g)     s[nc][0] = -INFINITY;
                    if (col + 1 > wrow + g)     s[nc][1] = -INFINITY;
                    if (col     > wrow + g + 8) s[nc][2] = -INFINITY;
                    if (col + 1 > wrow + g + 8) s[nc][3] = -INFINITY;
                }
            }

            // ---- warp-local online softmax (P stays in s registers) ----
            float t0 = -INFINITY, t1 = -INFINITY;
#pragma unroll
            for (int nc = 0; nc < 8; nc++) {
                t0 = fmaxf(t0, fmaxf(s[nc][0], s[nc][1]));
                t1 = fmaxf(t1, fmaxf(s[nc][2], s[nc][3]));
            }
            t0 = fmaxf(t0, __shfl_xor_sync(0xffffffffu, t0, 1));
            t0 = fmaxf(t0, __shfl_xor_sync(0xffffffffu, t0, 2));
            t1 = fmaxf(t1, __shfl_xor_sync(0xffffffffu, t1, 1));
            t1 = fmaxf(t1, __shfl_xor_sync(0xffffffffu, t1, 2));
            float mn0 = fmaxf(mrow0, t0);
            float mn1 = fmaxf(mrow1, t1);
            float sc0 = __expf(mrow0 - mn0);
            float sc1 = __expf(mrow1 - mn1);
            mrow0 = mn0; mrow1 = mn1;

            float rs0 = 0.f, rs1 = 0.f;
#pragma unroll
            for (int nc = 0; nc < 8; nc++) {
                s[nc][0] = f2tf32f(__expf(s[nc][0] - mn0));
                s[nc][1] = f2tf32f(__expf(s[nc][1] - mn0));
                s[nc][2] = f2tf32f(__expf(s[nc][2] - mn1));
                s[nc][3] = f2tf32f(__expf(s[nc][3] - mn1));
                rs0 += s[nc][0] + s[nc][1];
                rs1 += s[nc][2] + s[nc][3];
            }
            rs0 += __shfl_xor_sync(0xffffffffu, rs0, 1);
            rs0 += __shfl_xor_sync(0xffffffffu, rs0, 2);
            rs1 += __shfl_xor_sync(0xffffffffu, rs1, 1);
            rs1 += __shfl_xor_sync(0xffffffffu, rs1, 2);
            lrow0 = lrow0 * sc0 + rs0;
            lrow1 = lrow1 * sc1 + rs1;
#pragma unroll
            for (int nc = 0; nc < 8; nc++) {
                o[nc][0] *= sc0; o[nc][1] *= sc0;
                o[nc][2] *= sc1; o[nc][3] *= sc1;
            }

            // ---- O += P V (A-fragment from s regs, permuted V rows) ----
#pragma unroll
            for (int j = 0; j < 8; j++) {
                uint32_t a[4];
                a[0] = __float_as_uint(s[j][0]);
                a[1] = __float_as_uint(s[j][2]);
                a[2] = __float_as_uint(s[j][1]);
                a[3] = __float_as_uint(s[j][3]);
                const int vr0 = j * 8 + 2 * tig;     // sigma(8j + tig)
#pragma unroll
                for (int nc = 0; nc < 8; nc++) {
                    uint32_t b[2];
                    b[0] = __float_as_uint(vs[(vr0    ) * LDV + nc * 8 + g]);
                    b[1] = __float_as_uint(vs[(vr0 + 1) * LDV + nc * 8 + g]);
                    mma_tf32(o[nc], a, b);
                }
            }
        }
    }

    // normalize, tf32-round, write g_att [B,T,C]
    const int b = bh >> 4;
    const int h = bh & 15;
    const float inv0 = 1.f / lrow0;
    const float inv1 = 1.f / lrow1;
    const int t0r = wrow + g;
    const int t1r = wrow + g + 8;
#pragma unroll
    for (int nc = 0; nc < 8; nc++) {
        int d = h * DH + nc * 8 + 2 * tig;
        *(float2*)&g_att[((size_t)b * TLEN + t0r) * CDIM + d] =
            make_float2(f2tf32f(o[nc][0] * inv0), f2tf32f(o[nc][1] * inv0));
        *(float2*)&g_att[((size_t)b * TLEN + t1r) * CDIM + d] =
            make_float2(f2tf32f(o[nc][2] * inv1), f2tf32f(o[nc][3] * inv1));
    }
}

// ----------------------------------------------------------------------------
extern "C" void kernel_launch(void* const* d_in, const int* in_sizes, int n_in,
                              void* d_out, int out_size)
{
    const float* x  = (const float*)d_in[0];
    const float* Wq = (const float*)d_in[1];
    const float* Wk = (const float*)d_in[2];
    const float* Wv = (const float*)d_in[3];
    const float* Wo = (const float*)d_in[4];
    float* out = (float*)d_out;

    preround_kernel<<<dim3(4096, 5), 256>>>(x, Wq, Wk, Wv, Wo);

    cudaFuncSetAttribute(gemm_cp_kernel<1>,
                         cudaFuncAttributeMaxDynamicSharedMemorySize, GSMEM2);
    cudaFuncSetAttribute(gemm_cp_kernel<0>,
                         cudaFuncAttributeMaxDynamicSharedMemorySize, GSMEM2);

    gemm_cp_kernel<1><<<dim3(CDIM / 128, MROWS / 128, 3), 256, GSMEM2>>>(nullptr);

    cudaFuncSetAttribute(attn_mma_kernel,
                         cudaFuncAttributeMaxDynamicSharedMemorySize, ATT_SMEM);
    attn_mma_kernel<<<dim3(TLEN / QROWS, BDIM * NH), 256, ATT_SMEM>>>();

    gemm_cp_kernel<0><<<dim3(CDIM / 128, MROWS / 128, 1), 256, GSMEM2>>>(out);
}

// round 12
// speedup vs baseline: 1.0751x; 1.0205x over previous
#include <cuda_runtime.h>
#include <cstdint>
#include <math.h>

#define BDIM 2
#define TLEN 2048
#define CDIM 1024
#define NH   16
#define DH   64
#define MROWS (BDIM * TLEN)   // 4096

// Scratch (allocation-free rule: __device__ globals)
// g_q/g_k: tf32-rounded, COLUMN-PERMUTED within 8-col groups (q pre-scaled)
// g_v: tf32-rounded, plain layout
__device__ float g_q[(size_t)BDIM * NH * TLEN * DH];
__device__ float g_k[(size_t)BDIM * NH * TLEN * DH];
__device__ float g_v[(size_t)BDIM * NH * TLEN * DH];
__device__ float g_att[(size_t)MROWS * CDIM];          // [B,T,C], tf32-rounded
__device__ float g_xr[(size_t)MROWS * CDIM];           // tf32-rounded x
__device__ float g_wr[4][(size_t)CDIM * CDIM];         // tf32-rounded Wq,Wk,Wv,Wo

// ============================================================================
// helpers
// ============================================================================
__device__ __forceinline__ float f2tf32f(float f) {
    uint32_t r;
    asm("cvt.rna.tf32.f32 %0, %1;" : "=r"(r) : "f"(f));
    return __uint_as_float(r);
}
__device__ __forceinline__ float4 cvt4(float4 v) {
    return make_float4(f2tf32f(v.x), f2tf32f(v.y), f2tf32f(v.z), f2tf32f(v.w));
}
__device__ __forceinline__ void mma_tf32(float* d, const uint32_t* a,
                                         const uint32_t* b) {
    asm volatile(
        "mma.sync.aligned.m16n8k8.row.col.f32.tf32.tf32.f32 "
        "{%0,%1,%2,%3}, {%4,%5,%6,%7}, {%8,%9}, {%0,%1,%2,%3};"
        : "+f"(d[0]), "+f"(d[1]), "+f"(d[2]), "+f"(d[3])
        : "r"(a[0]), "r"(a[1]), "r"(a[2]), "r"(a[3]), "r"(b[0]), "r"(b[1]));
}
__device__ __forceinline__ uint32_t smem_u32(const void* p) {
    uint32_t a;
    asm("{ .reg .u64 t; cvta.to.shared.u64 t, %1; cvt.u32.u64 %0, t; }"
        : "=r"(a) : "l"(p));
    return a;
}
__device__ __forceinline__ void cp_async16(uint32_t saddr, const void* gptr) {
    asm volatile("cp.async.ca.shared.global [%0], [%1], 16;"
                 :: "r"(saddr), "l"(gptr) : "memory");
}
__device__ __forceinline__ void cp_commit() {
    asm volatile("cp.async.commit_group;" ::: "memory");
}
// permuted position of logical col c within its 8-col group
__device__ __forceinline__ int cperm(int c) {
    return 2 * (c & 3) + (c >> 2);
}

// ============================================================================
// preround: tf32-round x and the 4 weight matrices into scratch
// ============================================================================
__global__ void __launch_bounds__(256) preround_kernel(
    const float* __restrict__ x,  const float* __restrict__ Wq,
    const float* __restrict__ Wk, const float* __restrict__ Wv,
    const float* __restrict__ Wo)
{
    const int t = blockIdx.y;
    const float* src;
    float* dst;
    int n;
    if (t == 0) { src = x; dst = g_xr; n = MROWS * CDIM / 4; }
    else {
        src = (t == 1) ? Wq : (t == 2) ? Wk : (t == 3) ? Wv : Wo;
        dst = g_wr[t - 1];
        n = CDIM * CDIM / 4;
    }
    int idx = blockIdx.x * 256 + threadIdx.x;
    if (idx < n) ((float4*)dst)[idx] = cvt4(((const float4*)src)[idx]);
}

// ============================================================================
// cp.async 3-stage tf32 mma.sync GEMM.
// SCATTER=1: epilogue tf32-rounds; q pre-scaled 0.125; q/k stored with
// permuted columns (cperm) within each 8-col group, v plain.
// ============================================================================
#define BK2 32
#define LDT2 36
#define STAGES 3
#define NSTEP2 (CDIM / BK2)     // 32
#define GSMEM2 (STAGES * 128 * LDT2 * 2 * 4)   // 110592 B

template <int SCATTER>
__global__ void __launch_bounds__(256, 2) gemm_cp_kernel(float* __restrict__ Cout)
{
    extern __shared__ float smf[];
    const int K = CDIM;
    float* As = smf;                           // [STAGES][128][LDT2]
    float* Ws = smf + STAGES * 128 * LDT2;

    const float* Ap = SCATTER ? g_xr : g_att;
    const float* W  = g_wr[SCATTER ? blockIdx.z : 3];
    float* dst;
    if (SCATTER) {
        int z = blockIdx.z;
        dst = (z == 0) ? g_q : (z == 1) ? g_k : g_v;
    } else {
        dst = Cout;
    }
    const float oscale = (SCATTER && blockIdx.z == 0) ? 0.125f : 1.0f;
    const bool permute = SCATTER && (blockIdx.z < 2);   // q,k permuted

    const int bm0  = blockIdx.y * 128;
    const int bn0  = blockIdx.x * 128;
    const int tid  = threadIdx.x;
    const int lane = tid & 31;
    const int wid  = tid >> 5;
    const int g    = lane >> 2;
    const int tig  = lane & 3;
    const int wm   = (wid & 3) * 32;
    const int wn   = (wid >> 2) * 64;

    const uint32_t sbA = smem_u32(As);
    const uint32_t sbW = smem_u32(Ws);

    float d[2][8][4];
#pragma unroll
    for (int mc = 0; mc < 2; mc++)
#pragma unroll
        for (int nc = 0; nc < 8; nc++)
#pragma unroll
            for (int v = 0; v < 4; v++) d[mc][nc][v] = 0.f;

    auto issue = [&](int t, int slot) {
        const int k0 = t * BK2;
        const uint32_t ab = sbA + slot * 128 * LDT2 * 4;
        const uint32_t wb = sbW + slot * 128 * LDT2 * 4;
#pragma unroll
        for (int l = 0; l < 4; l++) {
            int idx = tid + l * 256;      // 0..1023
            int r   = idx >> 3;           // 0..127
            int c   = idx & 7;
            uint32_t so = (uint32_t)(r * LDT2 + c * 4) * 4;
            cp_async16(ab + so, &Ap[(size_t)(bm0 + r) * K + k0 + c * 4]);
            cp_async16(wb + so, &W [(size_t)(bn0 + r) * K + k0 + c * 4]);
        }
        cp_commit();
    };

    issue(0, 0);
    issue(1, 1);

    for (int s = 0; s < NSTEP2; s++) {
        if (s + 1 < NSTEP2) asm volatile("cp.async.wait_group 1;" ::: "memory");
        else                asm volatile("cp.async.wait_group 0;" ::: "memory");
        __syncthreads();
        if (s + 2 < NSTEP2) issue(s + 2, (s + 2) % STAGES);

        const float* Ab = As + (s % STAGES) * 128 * LDT2;
        const float* Wb = Ws + (s % STAGES) * 128 * LDT2;
#pragma unroll
        for (int kk8 = 0; kk8 < 4; kk8++) {
            const int kk = kk8 * 8;
            uint32_t a[2][4];
#pragma unroll
            for (int mc = 0; mc < 2; mc++) {
                int row = wm + mc * 16 + g;
                a[mc][0] = __float_as_uint(Ab[(row    ) * LDT2 + kk + tig]);
                a[mc][1] = __float_as_uint(Ab[(row + 8) * LDT2 + kk + tig]);
                a[mc][2] = __float_as_uint(Ab[(row    ) * LDT2 + kk + tig + 4]);
                a[mc][3] = __float_as_uint(Ab[(row + 8) * LDT2 + kk + tig + 4]);
            }
#pragma unroll
            for (int nc = 0; nc < 8; nc++) {
                uint32_t b[2];
                int row = wn + nc * 8 + g;
                b[0] = __float_as_uint(Wb[row * LDT2 + kk + tig]);
                b[1] = __float_as_uint(Wb[row * LDT2 + kk + tig + 4]);
                mma_tf32(d[0][nc], a[0], b);
                mma_tf32(d[1][nc], a[1], b);
            }
        }
    }

#pragma unroll
    for (int mc = 0; mc < 2; mc++) {
#pragma unroll
        for (int nc = 0; nc < 8; nc++) {
            int n = bn0 + wn + nc * 8 + tig * 2;
#pragma unroll
            for (int rr = 0; rr < 2; rr++) {
                int m = bm0 + wm + mc * 16 + g + rr * 8;
                if (SCATTER) {
                    float v0 = f2tf32f(d[mc][nc][rr * 2 + 0] * oscale);
                    float v1 = f2tf32f(d[mc][nc][rr * 2 + 1] * oscale);
                    int bb = m >> 11;
                    int tt = m & 2047;
                    int hh = n >> 6;
                    int dd = n & 63;
                    float* p = dst + (((size_t)bb * NH + hh) * TLEN + tt) * DH;
                    if (permute) {
                        int grp = dd & 56;
                        int c   = dd & 7;
                        p[grp + cperm(c)]     = v0;
                        p[grp + cperm(c + 1)] = v1;
                    } else {
                        *(float2*)&p[dd] = make_float2(v0, v1);
                    }
                } else {
                    *(float2*)&dst[(size_t)m * CDIM + n] =
                        make_float2(d[mc][nc][rr * 2 + 0], d[mc][nc][rr * 2 + 1]);
                }
            }
        }
    }
}

// ============================================================================
// tf32 mma.sync causal flash attention v6 — register-resident P,
// double-buffered cp.async K/V, column-permuted Q/K => LDS.64 QK fragments.
// LDQ=LDK=72 (bank 8g+2tig, conflict-free); V plain LDV=68.
// smem: Q 36864 + 2*(K 18432 + V 17408) = 108544 B -> 2 CTAs/SM.
// ============================================================================
#define LDQ 72
#define LDK 72
#define LDV 68
#define QROWS 128
#define KVSTAGE (64 * LDK + 64 * LDV)   // floats per stage = 8960
#define ATT_SMEM ((QROWS * LDQ + 2 * KVSTAGE) * 4)   // 108544 B

__global__ void __launch_bounds__(256, 2) attn_mma_kernel()
{
    extern __shared__ float sm[];
    float* qs = sm;                          // [128][LDQ] (permuted cols)
    float* kvb = qs + QROWS * LDQ;           // [2][ K[64][LDK] | V[64][LDV] ]
    const uint32_t sq  = smem_u32(qs);
    const uint32_t skv = smem_u32(kvb);

    const int qt = (gridDim.x - 1) - blockIdx.x;   // big tiles first
    const int bh = blockIdx.y;
    const float* qg = g_q + (size_t)bh * TLEN * DH;
    const float* kg = g_k + (size_t)bh * TLEN * DH;
    const float* vg = g_v + (size_t)bh * TLEN * DH;

    const int tid  = threadIdx.x;
    const int lane = tid & 31;
    const int wid  = tid >> 5;
    const int g    = lane >> 2;
    const int tig  = lane & 3;

    auto issue_kv = [&](int kt, int b) {
        const uint32_t kb = skv + (uint32_t)(b * KVSTAGE) * 4;
        const uint32_t vb = kb + (uint32_t)(64 * LDK) * 4;
#pragma unroll
        for (int l = 0; l < 4; l++) {
            int idx = tid + l * 256;
            int r   = idx >> 4;
            int c   = idx & 15;
            cp_async16(kb + (uint32_t)(r * LDK + c * 4) * 4,
                       &kg[(size_t)(kt * 64 + r) * DH + c * 4]);
            cp_async16(vb + (uint32_t)(r * LDV + c * 4) * 4,
                       &vg[(size_t)(kt * 64 + r) * DH + c * 4]);
        }
        cp_commit();
    };

    // group 0: Q tile + K/V tile 0
#pragma unroll
    for (int l = 0; l < 8; l++) {
        int idx = tid + l * 256;
        int r   = idx >> 4;
        int c   = idx & 15;
        cp_async16(sq + (uint32_t)(r * LDQ + c * 4) * 4,
                   &qg[(size_t)(qt * QROWS + r) * DH + c * 4]);
    }
    issue_kv(0, 0);

    const int wrow = qt * QROWS + wid * 16;
    float mrow0 = -INFINITY, mrow1 = -INFINITY;
    float lrow0 = 0.f, lrow1 = 0.f;
    float o[8][4];
#pragma unroll
    for (int nc = 0; nc < 8; nc++)
#pragma unroll
        for (int v = 0; v < 4; v++) o[nc][v] = 0.f;

    const int ktmax = 2 * qt + 1;
    for (int kt = 0; kt <= ktmax; kt++) {
        asm volatile("cp.async.wait_group 0;" ::: "memory");
        __syncthreads();
        if (kt < ktmax) issue_kv(kt + 1, (kt + 1) & 1);

        const float* ks = kvb + (kt & 1) * KVSTAGE;
        const float* vs = ks + 64 * LDK;

        if (kt * 64 <= wrow + 15) {
            // ---- S = Q K^T (LDS.64 fragment loads via column permutation) ----
            float s[8][4];
#pragma unroll
            for (int nc = 0; nc < 8; nc++)
#pragma unroll
                for (int v = 0; v < 4; v++) s[nc][v] = 0.f;
#pragma unroll
            for (int kk8 = 0; kk8 < 8; kk8++) {
                const int kk = kk8 * 8;
                float2 aq0 = *(const float2*)&qs[(wid * 16 + g    ) * LDQ + kk + 2 * tig];
                float2 aq1 = *(const float2*)&qs[(wid * 16 + g + 8) * LDQ + kk + 2 * tig];
                uint32_t a[4];
                a[0] = __float_as_uint(aq0.x);
                a[1] = __float_as_uint(aq1.x);
                a[2] = __float_as_uint(aq0.y);
                a[3] = __float_as_uint(aq1.y);
#pragma unroll
                for (int nc = 0; nc < 8; nc++) {
                    float2 bk = *(const float2*)&ks[(nc * 8 + g) * LDK + kk + 2 * tig];
                    uint32_t b[2];
                    b[0] = __float_as_uint(bk.x);
                    b[1] = __float_as_uint(bk.y);
                    mma_tf32(s[nc], a, b);
                }
            }

            // ---- causal mask ----
            if (kt * 64 + 63 > wrow) {
#pragma unroll
                for (int nc = 0; nc < 8; nc++) {
                    int col = kt * 64 + nc * 8 + 2 * tig;
                    if (col     > wrow + g)     s[nc][0] = -INFINITY;
                    if (col + 1 > wrow + g)     s[nc][1] = -INFINITY;
                    if (col     > wrow + g + 8) s[nc][2] = -INFINITY;
                    if (col + 1 > wrow + g + 8) s[nc][3] = -INFINITY;
                }
            }

            // ---- warp-local online softmax (P in registers; HW truncates
            //      fp32->tf32 in mma, so no explicit cvt needed) ----
            float t0 = -INFINITY, t1 = -INFINITY;
#pragma unroll
            for (int nc = 0; nc < 8; nc++) {
                t0 = fmaxf(t0, fmaxf(s[nc][0], s[nc][1]));
                t1 = fmaxf(t1, fmaxf(s[nc][2], s[nc][3]));
            }
            t0 = fmaxf(t0, __shfl_xor_sync(0xffffffffu, t0, 1));
            t0 = fmaxf(t0, __shfl_xor_sync(0xffffffffu, t0, 2));
            t1 = fmaxf(t1, __shfl_xor_sync(0xffffffffu, t1, 1));
            t1 = fmaxf(t1, __shfl_xor_sync(0xffffffffu, t1, 2));
            float mn0 = fmaxf(mrow0, t0);
            float mn1 = fmaxf(mrow1, t1);
            float sc0 = __expf(mrow0 - mn0);
            float sc1 = __expf(mrow1 - mn1);
            mrow0 = mn0; mrow1 = mn1;

            float rs0 = 0.f, rs1 = 0.f;
#pragma unroll
            for (int nc = 0; nc < 8; nc++) {
                s[nc][0] = __expf(s[nc][0] - mn0);
                s[nc][1] = __expf(s[nc][1] - mn0);
                s[nc][2] = __expf(s[nc][2] - mn1);
                s[nc][3] = __expf(s[nc][3] - mn1);
                rs0 += s[nc][0] + s[nc][1];
                rs1 += s[nc][2] + s[nc][3];
            }
            rs0 += __shfl_xor_sync(0xffffffffu, rs0, 1);
            rs0 += __shfl_xor_sync(0xffffffffu, rs0, 2);
            rs1 += __shfl_xor_sync(0xffffffffu, rs1, 1);
            rs1 += __shfl_xor_sync(0xffffffffu, rs1, 2);
            lrow0 = lrow0 * sc0 + rs0;
            lrow1 = lrow1 * sc1 + rs1;
#pragma unroll
            for (int nc = 0; nc < 8; nc++) {
                o[nc][0] *= sc0; o[nc][1] *= sc0;
                o[nc][2] *= sc1; o[nc][3] *= sc1;
            }

            // ---- O += P V (A-fragment from s regs, permuted V rows) ----
#pragma unroll
            for (int j = 0; j < 8; j++) {
                uint32_t a[4];
                a[0] = __float_as_uint(s[j][0]);
                a[1] = __float_as_uint(s[j][2]);
                a[2] = __float_as_uint(s[j][1]);
                a[3] = __float_as_uint(s[j][3]);
                const int vr0 = j * 8 + 2 * tig;     // sigma(8j + tig)
#pragma unroll
                for (int nc = 0; nc < 8; nc++) {
                    uint32_t b[2];
                    b[0] = __float_as_uint(vs[(vr0    ) * LDV + nc * 8 + g]);
                    b[1] = __float_as_uint(vs[(vr0 + 1) * LDV + nc * 8 + g]);
                    mma_tf32(o[nc], a, b);
                }
            }
        }
    }

    // normalize, tf32-round, write g_att [B,T,C]
    const int b = bh >> 4;
    const int h = bh & 15;
    const float inv0 = 1.f / lrow0;
    const float inv1 = 1.f / lrow1;
    const int t0r = wrow + g;
    const int t1r = wrow + g + 8;
#pragma unroll
    for (int nc = 0; nc < 8; nc++) {
        int d = h * DH + nc * 8 + 2 * tig;
        *(float2*)&g_att[((size_t)b * TLEN + t0r) * CDIM + d] =
            make_float2(f2tf32f(o[nc][0] * inv0), f2tf32f(o[nc][1] * inv0));
        *(float2*)&g_att[((size_t)b * TLEN + t1r) * CDIM + d] =
            make_float2(f2tf32f(o[nc][2] * inv1), f2tf32f(o[nc][3] * inv1));
    }
}

// ----------------------------------------------------------------------------
extern "C" void kernel_launch(void* const* d_in, const int* in_sizes, int n_in,
                              void* d_out, int out_size)
{
    const float* x  = (const float*)d_in[0];
    const float* Wq = (const float*)d_in[1];
    const float* Wk = (const float*)d_in[2];
    const float* Wv = (const float*)d_in[3];
    const float* Wo = (const float*)d_in[4];
    float* out = (float*)d_out;

    preround_kernel<<<dim3(4096, 5), 256>>>(x, Wq, Wk, Wv, Wo);

    cudaFuncSetAttribute(gemm_cp_kernel<1>,
                         cudaFuncAttributeMaxDynamicSharedMemorySize, GSMEM2);
    cudaFuncSetAttribute(gemm_cp_kernel<0>,
                         cudaFuncAttributeMaxDynamicSharedMemorySize, GSMEM2);

    gemm_cp_kernel<1><<<dim3(CDIM / 128, MROWS / 128, 3), 256, GSMEM2>>>(nullptr);

    cudaFuncSetAttribute(attn_mma_kernel,
                         cudaFuncAttributeMaxDynamicSharedMemorySize, ATT_SMEM);
    attn_mma_kernel<<<dim3(TLEN / QROWS, BDIM * NH), 256, ATT_SMEM>>>();

    gemm_cp_kernel<0><<<dim3(CDIM / 128, MROWS / 128, 1), 256, GSMEM2>>>(out);
}

// round 13
// speedup vs baseline: 1.7820x; 1.6576x over previous
#include <cuda_runtime.h>
#include <cuda_fp16.h>
#include <cstdint>
#include <math.h>

#define BDIM 2
#define TLEN 2048
#define CDIM 1024
#define NH   16
#define DH   64
#define MROWS (BDIM * TLEN)   // 4096

// Scratch (allocation-free rule: __device__ globals)
// halves; k-dims permuted within 16-blocks by p16 (see below)
__device__ __half g_qh[(size_t)BDIM * NH * TLEN * DH];   // [B,H,T,Dh], d-permuted, prescaled
__device__ __half g_kh[(size_t)BDIM * NH * TLEN * DH];   // [B,H,T,Dh], d-permuted
__device__ __half g_vth[(size_t)BDIM * NH * DH * TLEN];  // [B,H,Dh,T] transposed, key-permuted
__device__ __half g_atth[(size_t)MROWS * CDIM];          // [B,T,C], C-permuted
__device__ __half g_xh[(size_t)MROWS * CDIM];            // k-permuted
__device__ __half g_wh[4][(size_t)CDIM * CDIM];          // k-permuted

// ============================================================================
// helpers
// ============================================================================
__device__ __forceinline__ void mma_f16(float* d, const uint32_t* a,
                                        const uint32_t* b) {
    asm volatile(
        "mma.sync.aligned.m16n8k16.row.col.f32.f16.f16.f32 "
        "{%0,%1,%2,%3}, {%4,%5,%6,%7}, {%8,%9}, {%0,%1,%2,%3};"
        : "+f"(d[0]), "+f"(d[1]), "+f"(d[2]), "+f"(d[3])
        : "r"(a[0]), "r"(a[1]), "r"(a[2]), "r"(a[3]), "r"(b[0]), "r"(b[1]));
}
__device__ __forceinline__ uint32_t packh2(float lo, float hi) {
    __half2 h = __floats2half2_rn(lo, hi);
    return *(uint32_t*)&h;
}
__device__ __forceinline__ uint32_t smem_u32(const void* p) {
    uint32_t a;
    asm("{ .reg .u64 t; cvta.to.shared.u64 t, %1; cvt.u32.u64 %0, t; }"
        : "=r"(a) : "l"(p));
    return a;
}
__device__ __forceinline__ void cp_async16(uint32_t saddr, const void* gptr) {
    asm volatile("cp.async.ca.shared.global [%0], [%1], 16;"
                 :: "r"(saddr), "l"(gptr) : "memory");
}
__device__ __forceinline__ void cp_commit() {
    asm volatile("cp.async.commit_group;" ::: "memory");
}
// permuted position of logical index c within a 16-block:
// positions 4t..4t+3 hold logical {2t, 2t+1, 2t+8, 2t+9}
__device__ __forceinline__ int p16(int c) {
    return 2 * (c & 7) - (c & 1) + 2 * (c >> 3);
}

// ============================================================================
// preround: fp16-convert x and weights, k-permuted within 16-blocks
// ============================================================================
__global__ void __launch_bounds__(256) preround_kernel(
    const float* __restrict__ x,  const float* __restrict__ Wq,
    const float* __restrict__ Wk, const float* __restrict__ Wv,
    const float* __restrict__ Wo)
{
    const int t = blockIdx.y;
    const float* src;
    __half* dst;
    int n;
    if (t == 0) { src = x; dst = g_xh; n = MROWS * CDIM / 4; }
    else {
        src = (t == 1) ? Wq : (t == 2) ? Wk : (t == 3) ? Wv : Wo;
        dst = g_wh[t - 1];
        n = CDIM * CDIM / 4;
    }
    int idx = blockIdx.x * 256 + threadIdx.x;
    if (idx < n) {
        float4 v = ((const float4*)src)[idx];
        int f = idx * 4;
        int c = f & 15;                       // 0,4,8,12
        size_t blk = ((size_t)(f >> 4)) << 3; // half2 base of 16-block
        __half2* d2 = (__half2*)dst;
        d2[blk + (c & 7) + (c >> 3)]                 = __floats2half2_rn(v.x, v.y);
        d2[blk + ((c + 2) & 7) + ((c + 2) >> 3)]     = __floats2half2_rn(v.z, v.w);
    }
}

// ============================================================================
// fp16 m16n8k16 cp.async 3-stage GEMM: C[m,n] = sum_k A[m,k] * W[n,k]
// CTA 128x128, BK=32 (2 k16-steps), 8 warps (4x2), warp tile 32x64.
// SCATTER=1: z=0 -> q (prescaled 0.125, d-permuted half), z=1 -> k (d-perm),
//            z=2 -> v (transposed [d][t], key-permuted).
// SCATTER=0: fp32 out.
// ============================================================================
#define BK2 32
#define LDT2H 48
#define STAGES 3
#define NSTEP2 (CDIM / BK2)     // 32
#define GSMEM2 (STAGES * 128 * LDT2H * 2 * 2)   // 73728 B

template <int SCATTER>
__global__ void __launch_bounds__(256, 2) gemm_h_kernel(float* __restrict__ Cout)
{
    extern __shared__ __half smh[];
    const int K = CDIM;
    __half* As = smh;                          // [STAGES][128][LDT2H]
    __half* Ws = smh + STAGES * 128 * LDT2H;

    const __half* Ap = SCATTER ? g_xh : g_atth;
    const __half* W  = g_wh[SCATTER ? blockIdx.z : 3];
    const int z = SCATTER ? blockIdx.z : 3;
    const float oscale = (SCATTER && z == 0) ? 0.125f : 1.0f;

    const int bm0  = blockIdx.y * 128;
    const int bn0  = blockIdx.x * 128;
    const int tid  = threadIdx.x;
    const int lane = tid & 31;
    const int wid  = tid >> 5;
    const int g    = lane >> 2;
    const int tig  = lane & 3;
    const int wm   = (wid & 3) * 32;
    const int wn   = (wid >> 2) * 64;

    const uint32_t sbA = smem_u32(As);
    const uint32_t sbW = smem_u32(Ws);

    float d[2][8][4];
#pragma unroll
    for (int mc = 0; mc < 2; mc++)
#pragma unroll
        for (int nc = 0; nc < 8; nc++)
#pragma unroll
            for (int v = 0; v < 4; v++) d[mc][nc][v] = 0.f;

    auto issue = [&](int t, int slot) {
        const int k0 = t * BK2;
        const uint32_t ab = sbA + (uint32_t)slot * 128 * LDT2H * 2;
        const uint32_t wb = sbW + (uint32_t)slot * 128 * LDT2H * 2;
#pragma unroll
        for (int l = 0; l < 2; l++) {
            int idx = tid + l * 256;      // 0..511
            int r   = idx >> 2;           // 0..127
            int c   = idx & 3;            // 16B chunk (8 halves)
            uint32_t so = (uint32_t)(r * LDT2H + c * 8) * 2;
            cp_async16(ab + so, &Ap[(size_t)(bm0 + r) * K + k0 + c * 8]);
            cp_async16(wb + so, &W [(size_t)(bn0 + r) * K + k0 + c * 8]);
        }
        cp_commit();
    };

    issue(0, 0);
    issue(1, 1);

    for (int s = 0; s < NSTEP2; s++) {
        if (s + 1 < NSTEP2) asm volatile("cp.async.wait_group 1;" ::: "memory");
        else                asm volatile("cp.async.wait_group 0;" ::: "memory");
        __syncthreads();
        if (s + 2 < NSTEP2) issue(s + 2, (s + 2) % STAGES);

        const __half* Ab = As + (s % STAGES) * 128 * LDT2H;
        const __half* Wb = Ws + (s % STAGES) * 128 * LDT2H;
#pragma unroll
        for (int ks = 0; ks < 2; ks++) {
            uint32_t a[2][4];
#pragma unroll
            for (int mc = 0; mc < 2; mc++) {
                int row = wm + mc * 16 + g;
                uint2 lo = *(const uint2*)&Ab[row * LDT2H + ks * 16 + 4 * tig];
                uint2 hi = *(const uint2*)&Ab[(row + 8) * LDT2H + ks * 16 + 4 * tig];
                a[mc][0] = lo.x; a[mc][1] = hi.x; a[mc][2] = lo.y; a[mc][3] = hi.y;
            }
#pragma unroll
            for (int nc = 0; nc < 8; nc++) {
                uint2 bb = *(const uint2*)&Wb[(wn + nc * 8 + g) * LDT2H + ks * 16 + 4 * tig];
                uint32_t b[2] = {bb.x, bb.y};
                mma_f16(d[0][nc], a[0], b);
                mma_f16(d[1][nc], a[1], b);
            }
        }
    }

#pragma unroll
    for (int mc = 0; mc < 2; mc++) {
#pragma unroll
        for (int nc = 0; nc < 8; nc++) {
            int n = bn0 + wn + nc * 8 + tig * 2;
#pragma unroll
            for (int rr = 0; rr < 2; rr++) {
                int m = bm0 + wm + mc * 16 + g + rr * 8;
                float v0 = d[mc][nc][rr * 2 + 0];
                float v1 = d[mc][nc][rr * 2 + 1];
                if (SCATTER) {
                    v0 *= oscale; v1 *= oscale;
                    int bb = m >> 11;
                    int tt = m & 2047;
                    int hh = n >> 6;
                    int dd = n & 63;                 // even
                    if (z < 2) {
                        // q/k: [B,H,T,Dh] half, d permuted within 16-blocks
                        __half* base = (z == 0 ? g_qh : g_kh)
                            + (((size_t)bb * NH + hh) * TLEN + tt) * DH;
                        int r16 = dd & 15;
                        ((__half2*)base)[(dd >> 4) * 8 + (r16 & 7) + (r16 >> 3)]
                            = __floats2half2_rn(v0, v1);
                    } else {
                        // v: transposed [B,H,Dh,T], key (t) permuted
                        int tperm = (tt & ~15) + p16(tt & 15);
                        __half* base = g_vth + ((size_t)bb * NH + hh) * DH * TLEN;
                        base[(size_t)dd * TLEN + tperm]       = __float2half_rn(v0);
                        base[(size_t)(dd + 1) * TLEN + tperm] = __float2half_rn(v1);
                    }
                } else {
                    *(float2*)&Cout[(size_t)m * CDIM + n] = make_float2(v0, v1);
                }
            }
        }
    }
}

// ============================================================================
// fp16 m16n8k16 causal flash attention — register-resident P,
// double-buffered cp.async K/V, all fragment loads LDS.64 via permuted layout.
// smem halves: Q 128x80, per stage K 64x80 + V 64x80. 61440 B -> 2 CTAs/SM.
// ============================================================================
#define LDAH 80
#define QROWS 128
#define KVSTAGEH (2 * 64 * LDAH)        // halves per K+V stage = 10240
#define ATT_SMEM ((QROWS * LDAH + 2 * KVSTAGEH) * 2)   // 61440 B

__global__ void __launch_bounds__(256, 2) attn_h_kernel()
{
    extern __shared__ __half smh[];
    __half* qs  = smh;                       // [128][LDAH] (perm d)
    __half* kvb = qs + QROWS * LDAH;         // [2][ K[64][LDAH] | V[64][LDAH] ]
    const uint32_t sq  = smem_u32(qs);
    const uint32_t skv = smem_u32(kvb);

    const int qt = (gridDim.x - 1) - blockIdx.x;   // big tiles first
    const int bh = blockIdx.y;
    const __half* qg = g_qh + (size_t)bh * TLEN * DH;
    const __half* kg = g_kh + (size_t)bh * TLEN * DH;
    const __half* vg = g_vth + (size_t)bh * DH * TLEN;  // [d][t]

    const int tid  = threadIdx.x;
    const int lane = tid & 31;
    const int wid  = tid >> 5;
    const int g    = lane >> 2;
    const int tig  = lane & 3;

    auto issue_kv = [&](int kt, int b) {
        const uint32_t kb = skv + (uint32_t)(b * KVSTAGEH) * 2;
        const uint32_t vb = kb + (uint32_t)(64 * LDAH) * 2;
#pragma unroll
        for (int l = 0; l < 2; l++) {
            int idx = tid + l * 256;        // 0..511
            int r   = idx >> 3;             // 0..63
            int c   = idx & 7;              // 16B chunk (8 halves)
            cp_async16(kb + (uint32_t)(r * LDAH + c * 8) * 2,
                       &kg[(size_t)(kt * 64 + r) * DH + c * 8]);
            cp_async16(vb + (uint32_t)(r * LDAH + c * 8) * 2,
                       &vg[(size_t)r * TLEN + kt * 64 + c * 8]);
        }
        cp_commit();
    };

    // group 0: Q tile (1024 chunks) + K/V tile 0
#pragma unroll
    for (int l = 0; l < 4; l++) {
        int idx = tid + l * 256;
        int r   = idx >> 3;                 // 0..127
        int c   = idx & 7;
        cp_async16(sq + (uint32_t)(r * LDAH + c * 8) * 2,
                   &qg[(size_t)(qt * QROWS + r) * DH + c * 8]);
    }
    issue_kv(0, 0);

    const int wrow = qt * QROWS + wid * 16;
    float mrow0 = -INFINITY, mrow1 = -INFINITY;
    float lrow0 = 0.f, lrow1 = 0.f;
    float o[8][4];
#pragma unroll
    for (int nc = 0; nc < 8; nc++)
#pragma unroll
        for (int v = 0; v < 4; v++) o[nc][v] = 0.f;

    const int ktmax = 2 * qt + 1;
    for (int kt = 0; kt <= ktmax; kt++) {
        asm volatile("cp.async.wait_group 0;" ::: "memory");
        __syncthreads();
        if (kt < ktmax) issue_kv(kt + 1, (kt + 1) & 1);

        const __half* ks = kvb + (kt & 1) * KVSTAGEH;
        const __half* vs = ks + 64 * LDAH;

        if (kt * 64 <= wrow + 15) {
            // ---- S = Q K^T (4 k16-steps over Dh=64) ----
            float s[8][4];
#pragma unroll
            for (int nc = 0; nc < 8; nc++)
#pragma unroll
                for (int v = 0; v < 4; v++) s[nc][v] = 0.f;
#pragma unroll
            for (int j = 0; j < 4; j++) {
                uint2 q0 = *(const uint2*)&qs[(wid * 16 + g) * LDAH + 16 * j + 4 * tig];
                uint2 q1 = *(const uint2*)&qs[(wid * 16 + g + 8) * LDAH + 16 * j + 4 * tig];
                uint32_t a[4] = {q0.x, q1.x, q0.y, q1.y};
#pragma unroll
                for (int nc = 0; nc < 8; nc++) {
                    uint2 bk = *(const uint2*)&ks[(nc * 8 + g) * LDAH + 16 * j + 4 * tig];
                    uint32_t b[2] = {bk.x, bk.y};
                    mma_f16(s[nc], a, b);
                }
            }

            // ---- causal mask ----
            if (kt * 64 + 63 > wrow) {
#pragma unroll
                for (int nc = 0; nc < 8; nc++) {
                    int col = kt * 64 + nc * 8 + 2 * tig;
                    if (col     > wrow + g)     s[nc][0] = -INFINITY;
                    if (col + 1 > wrow + g)     s[nc][1] = -INFINITY;
                    if (col     > wrow + g + 8) s[nc][2] = -INFINITY;
                    if (col + 1 > wrow + g + 8) s[nc][3] = -INFINITY;
                }
            }

            // ---- warp-local online softmax ----
            float t0 = -INFINITY, t1 = -INFINITY;
#pragma unroll
            for (int nc = 0; nc < 8; nc++) {
                t0 = fmaxf(t0, fmaxf(s[nc][0], s[nc][1]));
                t1 = fmaxf(t1, fmaxf(s[nc][2], s[nc][3]));
            }
            t0 = fmaxf(t0, __shfl_xor_sync(0xffffffffu, t0, 1));
            t0 = fmaxf(t0, __shfl_xor_sync(0xffffffffu, t0, 2));
            t1 = fmaxf(t1, __shfl_xor_sync(0xffffffffu, t1, 1));
            t1 = fmaxf(t1, __shfl_xor_sync(0xffffffffu, t1, 2));
            float mn0 = fmaxf(mrow0, t0);
            float mn1 = fmaxf(mrow1, t1);
            float sc0 = __expf(mrow0 - mn0);
            float sc1 = __expf(mrow1 - mn1);
            mrow0 = mn0; mrow1 = mn1;

            float rs0 = 0.f, rs1 = 0.f;
#pragma unroll
            for (int nc = 0; nc < 8; nc++) {
                s[nc][0] = __expf(s[nc][0] - mn0);
                s[nc][1] = __expf(s[nc][1] - mn0);
                s[nc][2] = __expf(s[nc][2] - mn1);
                s[nc][3] = __expf(s[nc][3] - mn1);
                rs0 += s[nc][0] + s[nc][1];
                rs1 += s[nc][2] + s[nc][3];
            }
            rs0 += __shfl_xor_sync(0xffffffffu, rs0, 1);
            rs0 += __shfl_xor_sync(0xffffffffu, rs0, 2);
            rs1 += __shfl_xor_sync(0xffffffffu, rs1, 1);
            rs1 += __shfl_xor_sync(0xffffffffu, rs1, 2);
            lrow0 = lrow0 * sc0 + rs0;
            lrow1 = lrow1 * sc1 + rs1;
#pragma unroll
            for (int nc = 0; nc < 8; nc++) {
                o[nc][0] *= sc0; o[nc][1] *= sc0;
                o[nc][2] *= sc1; o[nc][3] *= sc1;
            }

            // ---- O += P V : A packed from softmax regs, B = V^T LDS.64 ----
#pragma unroll
            for (int j = 0; j < 4; j++) {
                uint32_t a[4];
                a[0] = packh2(s[2 * j][0],     s[2 * j][1]);
                a[1] = packh2(s[2 * j][2],     s[2 * j][3]);
                a[2] = packh2(s[2 * j + 1][0], s[2 * j + 1][1]);
                a[3] = packh2(s[2 * j + 1][2], s[2 * j + 1][3]);
#pragma unroll
                for (int nc = 0; nc < 8; nc++) {
                    uint2 bv = *(const uint2*)&vs[(nc * 8 + g) * LDAH + 16 * j + 4 * tig];
                    uint32_t b[2] = {bv.x, bv.y};
                    mma_f16(o[nc], a, b);
                }
            }
        }
    }

    // normalize, write g_atth [B,T,C] half, C permuted within 16-blocks
    const int b = bh >> 4;
    const int h = bh & 15;
    const float inv0 = 1.f / lrow0;
    const float inv1 = 1.f / lrow1;
    const int t0r = wrow + g;
    const int t1r = wrow + g + 8;
#pragma unroll
    for (int nc = 0; nc < 8; nc++) {
        int dd  = h * DH + nc * 8 + 2 * tig;    // even
        int r16 = dd & 15;
        int h2i = (dd >> 4) * 8 + (r16 & 7) + (r16 >> 3);
        ((__half2*)&g_atth[((size_t)b * TLEN + t0r) * CDIM])[h2i]
            = __floats2half2_rn(o[nc][0] * inv0, o[nc][1] * inv0);
        ((__half2*)&g_atth[((size_t)b * TLEN + t1r) * CDIM])[h2i]
            = __floats2half2_rn(o[nc][2] * inv1, o[nc][3] * inv1);
    }
}

// ----------------------------------------------------------------------------
extern "C" void kernel_launch(void* const* d_in, const int* in_sizes, int n_in,
                              void* d_out, int out_size)
{
    const float* x  = (const float*)d_in[0];
    const float* Wq = (const float*)d_in[1];
    const float* Wk = (const float*)d_in[2];
    const float* Wv = (const float*)d_in[3];
    const float* Wo = (const float*)d_in[4];
    float* out = (float*)d_out;

    preround_kernel<<<dim3(4096, 5), 256>>>(x, Wq, Wk, Wv, Wo);

    cudaFuncSetAttribute(gemm_h_kernel<1>,
                         cudaFuncAttributeMaxDynamicSharedMemorySize, GSMEM2);
    cudaFuncSetAttribute(gemm_h_kernel<0>,
                         cudaFuncAttributeMaxDynamicSharedMemorySize, GSMEM2);

    gemm_h_kernel<1><<<dim3(CDIM / 128, MROWS / 128, 3), 256, GSMEM2>>>(nullptr);

    cudaFuncSetAttribute(attn_h_kernel,
                         cudaFuncAttributeMaxDynamicSharedMemorySize, ATT_SMEM);
    attn_h_kernel<<<dim3(TLEN / QROWS, BDIM * NH), 256, ATT_SMEM>>>();

    gemm_h_kernel<0><<<dim3(CDIM / 128, MROWS / 128, 1), 256, GSMEM2>>>(out);
}